// round 3
// baseline (speedup 1.0000x reference)
#include <cuda_runtime.h>
#include <math.h>
#include <stdint.h>

// Problem constants
#define BB 2
#define SS 4096
#define FF 768
#define HH 12
#define DD 64
#define MM (BB * SS)       // 8192 rows
#define NQKV (3 * FF)      // 2304

// Scratch (allocation-free rule: __device__ globals)
__device__ float g_qkv[(size_t)MM * NQKV];   // [B*S, 3F]  ~75.5 MB
__device__ float g_att[(size_t)MM * FF];     // [B*S, F]   ~25 MB

// ---------------------------------------------------------------------------
// GEMM + bias: C[M,N] = A[M,K] @ W[K,N] + bias[N]
// 128x128x16 block tile, 256 threads, 8x8 per-thread microtile.
// A tile stored k-major (transposed) with stride 132 so the a-fragment is a
// broadcast LDS.128; B tile natural with lane-consecutive LDS.128.
// All dims here are multiples of the tile sizes (8192 / {2304,768} / 768).
// ---------------------------------------------------------------------------
__global__ __launch_bounds__(256) void gemm_bias_kernel(
    const float* __restrict__ A, const float* __restrict__ W,
    const float* __restrict__ bias, float* __restrict__ C,
    int M, int N, int K)
{
    __shared__ float Ast[16 * 132];
    __shared__ float Bsh[16 * 128];

    const int tid = threadIdx.x;
    const int ty = tid >> 4;       // 0..15
    const int tx = tid & 15;       // 0..15
    const int row0 = blockIdx.y * 128;
    const int col0 = blockIdx.x * 128;

    float acc[8][8];
#pragma unroll
    for (int i = 0; i < 8; i++)
#pragma unroll
        for (int j = 0; j < 8; j++) acc[i][j] = 0.f;

    for (int k0 = 0; k0 < K; k0 += 16) {
#pragma unroll
        for (int l = 0; l < 2; l++) {
            int f4 = tid + l * 256;
            // A: 128 rows x 16 cols = 512 float4
            int ar = f4 >> 2, ac = f4 & 3;
            float4 av = *(const float4*)(A + (size_t)(row0 + ar) * K + k0 + ac * 4);
            Ast[(ac * 4 + 0) * 132 + ar] = av.x;
            Ast[(ac * 4 + 1) * 132 + ar] = av.y;
            Ast[(ac * 4 + 2) * 132 + ar] = av.z;
            Ast[(ac * 4 + 3) * 132 + ar] = av.w;
            // B: 16 rows x 128 cols = 512 float4
            int br = f4 >> 5, bc = f4 & 31;
            *(float4*)(Bsh + br * 128 + bc * 4) =
                *(const float4*)(W + (size_t)(k0 + br) * N + col0 + bc * 4);
        }
        __syncthreads();

#pragma unroll
        for (int kk = 0; kk < 16; kk++) {
            float a[8], b[8];
            *(float4*)(a)     = *(const float4*)(Ast + kk * 132 + ty * 8);
            *(float4*)(a + 4) = *(const float4*)(Ast + kk * 132 + ty * 8 + 4);
            *(float4*)(b)     = *(const float4*)(Bsh + kk * 128 + tx * 8);
            *(float4*)(b + 4) = *(const float4*)(Bsh + kk * 128 + tx * 8 + 4);
#pragma unroll
            for (int i = 0; i < 8; i++)
#pragma unroll
                for (int j = 0; j < 8; j++)
                    acc[i][j] += a[i] * b[j];
        }
        __syncthreads();
    }

#pragma unroll
    for (int i = 0; i < 8; i++) {
        int r = row0 + ty * 8 + i;
#pragma unroll
        for (int g = 0; g < 2; g++) {
            int c = col0 + tx * 8 + g * 4;
            float4 o;
            o.x = acc[i][g * 4 + 0] + bias[c + 0];
            o.y = acc[i][g * 4 + 1] + bias[c + 1];
            o.z = acc[i][g * 4 + 2] + bias[c + 2];
            o.w = acc[i][g * 4 + 3] + bias[c + 3];
            *(float4*)(C + (size_t)r * N + c) = o;
        }
    }
}

// ---------------------------------------------------------------------------
// Flash attention (causal + key padding mask), fp32.
// One CTA = one (b, h, 64-query block). 256 threads, 4x4 microtiles.
// Qt/Kt stored d-major [64][68]; Vs k-major [64][68]; P written transposed
// Pt[k][q] so the P@V pass reads broadcast a-fragments. Stride 68 keeps all
// LDS.128 16B-aligned and the Pt scalar stores conflict-light.
// Dynamic smem: 4 * 64*68*4 = 69632 B.
// ---------------------------------------------------------------------------
__global__ __launch_bounds__(256) void attn_kernel(
    const float* __restrict__ qkv, const unsigned char* __restrict__ mask,
    float* __restrict__ att)
{
    extern __shared__ float sm[];
    float* Qt = sm;                 // [d=64][q=64] stride 68
    float* Kt = sm + 64 * 68;       // [d=64][k=64] stride 68
    float* Vs = sm + 2 * 64 * 68;   // [k=64][d=64] stride 68
    float* Pt = sm + 3 * 64 * 68;   // [k=64][q=64] stride 68

    const int qb = blockIdx.x;
    const int h  = blockIdx.y;
    const int b  = blockIdx.z;
    const int tid = threadIdx.x;
    const int ty = tid >> 4;
    const int tx = tid & 15;
    const int q0 = qb * 64;
    const size_t rowbase = (size_t)b * SS;

    // Load Q tile, transposed + pre-scaled by 1/sqrt(D)
#pragma unroll
    for (int l = 0; l < 4; l++) {
        int f4 = tid + l * 256;            // 0..1023
        int r = f4 >> 4;                   // q row 0..63
        int c = f4 & 15;                   // d/4
        float4 v = *(const float4*)(qkv + (rowbase + q0 + r) * NQKV + h * DD + c * 4);
        Qt[(c * 4 + 0) * 68 + r] = v.x * 0.125f;
        Qt[(c * 4 + 1) * 68 + r] = v.y * 0.125f;
        Qt[(c * 4 + 2) * 68 + r] = v.z * 0.125f;
        Qt[(c * 4 + 3) * 68 + r] = v.w * 0.125f;
    }

    float m_i[4], l_i[4], acc[4][4];
#pragma unroll
    for (int i = 0; i < 4; i++) {
        m_i[i] = -INFINITY;
        l_i[i] = 0.f;
#pragma unroll
        for (int j = 0; j < 4; j++) acc[i][j] = 0.f;
    }

    for (int kb = 0; kb <= qb; kb++) {
        const int k0 = kb * 64;
        __syncthreads();  // prev iter done with Kt/Vs/Pt; also publishes Qt on iter 0

        // Load K (transposed) and V tiles
#pragma unroll
        for (int l = 0; l < 4; l++) {
            int f4 = tid + l * 256;
            int r = f4 >> 4;               // k row
            int c = f4 & 15;               // d/4
            const float* kp = qkv + (rowbase + k0 + r) * NQKV + FF + h * DD + c * 4;
            float4 kv = *(const float4*)kp;
            Kt[(c * 4 + 0) * 68 + r] = kv.x;
            Kt[(c * 4 + 1) * 68 + r] = kv.y;
            Kt[(c * 4 + 2) * 68 + r] = kv.z;
            Kt[(c * 4 + 3) * 68 + r] = kv.w;
            *(float4*)(Vs + r * 68 + c * 4) = *(const float4*)(kp + FF);  // V is K + F
        }
        __syncthreads();

        // S = (Q/sqrt(D)) @ K^T  -- contraction over d
        float s[4][4];
#pragma unroll
        for (int i = 0; i < 4; i++)
#pragma unroll
            for (int j = 0; j < 4; j++) s[i][j] = 0.f;
#pragma unroll 8
        for (int kk = 0; kk < 64; kk++) {
            float a[4], bv[4];
            *(float4*)a  = *(const float4*)(Qt + kk * 68 + ty * 4);
            *(float4*)bv = *(const float4*)(Kt + kk * 68 + tx * 4);
#pragma unroll
            for (int i = 0; i < 4; i++)
#pragma unroll
                for (int j = 0; j < 4; j++)
                    s[i][j] += a[i] * bv[j];
        }

        // Masks: causal on the diagonal block, padding on keys
        uchar4 pmv = *(const uchar4*)(mask + (size_t)b * SS + k0 + tx * 4);
        unsigned char pm[4] = {pmv.x, pmv.y, pmv.z, pmv.w};
        const bool diag = (kb == qb);
#pragma unroll
        for (int j = 0; j < 4; j++) {
            int kidx = k0 + tx * 4 + j;
#pragma unroll
            for (int i = 0; i < 4; i++) {
                int qidx = q0 + ty * 4 + i;
                if (pm[j] || (diag && kidx > qidx)) s[i][j] = -INFINITY;
            }
        }

        // Online softmax (row stats shared across the 16 tx lanes via shfl)
#pragma unroll
        for (int i = 0; i < 4; i++) {
            float rmax = fmaxf(fmaxf(s[i][0], s[i][1]), fmaxf(s[i][2], s[i][3]));
#pragma unroll
            for (int off = 1; off < 16; off <<= 1)
                rmax = fmaxf(rmax, __shfl_xor_sync(0xffffffffu, rmax, off));
            float mnew = fmaxf(m_i[i], rmax);
            float alpha = __expf(m_i[i] - mnew);   // 0 on first block (m=-inf)
            m_i[i] = mnew;
            float rsum = 0.f;
#pragma unroll
            for (int j = 0; j < 4; j++) {
                float p = __expf(s[i][j] - mnew);
                s[i][j] = p;
                rsum += p;
            }
#pragma unroll
            for (int off = 1; off < 16; off <<= 1)
                rsum += __shfl_xor_sync(0xffffffffu, rsum, off);
            l_i[i] = l_i[i] * alpha + rsum;
#pragma unroll
            for (int j = 0; j < 4; j++) acc[i][j] *= alpha;
        }

        // Publish P transposed: Pt[k][q]
#pragma unroll
        for (int j = 0; j < 4; j++)
#pragma unroll
            for (int i = 0; i < 4; i++)
                Pt[(tx * 4 + j) * 68 + (ty * 4 + i)] = s[i][j];
        __syncthreads();

        // O += P @ V  -- contraction over k
#pragma unroll 8
        for (int kk = 0; kk < 64; kk++) {
            float a[4], bv[4];
            *(float4*)a  = *(const float4*)(Pt + kk * 68 + ty * 4);
            *(float4*)bv = *(const float4*)(Vs + kk * 68 + tx * 4);
#pragma unroll
            for (int i = 0; i < 4; i++)
#pragma unroll
                for (int j = 0; j < 4; j++)
                    acc[i][j] += a[i] * bv[j];
        }
    }

    // Epilogue: O / l, write [B*S, F] with column h*D + d
#pragma unroll
    for (int i = 0; i < 4; i++) {
        float inv = 1.f / l_i[i];
        float4 o;
        o.x = acc[i][0] * inv;
        o.y = acc[i][1] * inv;
        o.z = acc[i][2] * inv;
        o.w = acc[i][3] * inv;
        *(float4*)(att + (rowbase + q0 + ty * 4 + i) * FF + h * DD + tx * 4) = o;
    }
}

// ---------------------------------------------------------------------------
// Launch
// ---------------------------------------------------------------------------
extern "C" void kernel_launch(void* const* d_in, const int* in_sizes, int n_in,
                              void* d_out, int out_size)
{
    (void)in_sizes; (void)n_in; (void)out_size;
    const float*         x    = (const float*)d_in[0];
    const unsigned char* mask = (const unsigned char*)d_in[1];  // bool keys
    const float*         Wqkv = (const float*)d_in[2];
    const float*         bqkv = (const float*)d_in[3];
    const float*         Wout = (const float*)d_in[4];
    const float*         bout = (const float*)d_in[5];
    float*               out  = (float*)d_out;

    void* p;
    cudaGetSymbolAddress(&p, g_qkv);
    float* qkv = (float*)p;
    cudaGetSymbolAddress(&p, g_att);
    float* att = (float*)p;

    // 1) QKV projection: [8192,768] @ [768,2304] + bias
    dim3 g1(NQKV / 128, MM / 128);  // (18, 64)
    gemm_bias_kernel<<<g1, 256>>>(x, Wqkv, bqkv, qkv, MM, NQKV, FF);

    // 2) Causal flash attention
    const int smem = 4 * 64 * 68 * (int)sizeof(float);  // 69632 B
    cudaFuncSetAttribute(attn_kernel, cudaFuncAttributeMaxDynamicSharedMemorySize, smem);
    attn_kernel<<<dim3(SS / 64, HH, BB), 256, smem>>>(qkv, mask, att);

    // 3) Output projection: [8192,768] @ [768,768] + bias
    dim3 g2(FF / 128, MM / 128);    // (6, 64)
    gemm_bias_kernel<<<g2, 256>>>(att, Wout, bout, out, MM, FF, FF);
}